// round 10
// baseline (speedup 1.0000x reference)
#include <cuda_runtime.h>

#define IMG 256
#define MSAMP 1920
#define BATCH 64
#define NF 512                 // FFT size
#define NF2 (NF*NF)            // 262144
#define KSPLIT 12              // T-build K partitions (1920 = 12*160)

typedef unsigned long long u64t;

// ---------------------------------------------------------------------------
// Device scratch (static globals; no runtime allocation allowed)
// ---------------------------------------------------------------------------
__device__ float2 g_ex[MSAMP * NF];            // d_m/65536 * exp(+2i pi kx_m p)
__device__ float2 g_ey[MSAMP * NF];            // exp(+2i pi ky_m q)
__device__ float2 g_Tpart[KSPLIT * 256 * NF];  // K-split partials, p in [0,255] only
__device__ float2 g_Ttmp[NF2];                 // T after row FFT: [v][p]
__device__ float  g_TFr[NF2];                  // FFT2(T) (real!), stored [u][v]
__device__ float2 g_tw[NF];                    // W512^k = exp(-2i pi k/512)
__device__ float2 g_buf1[BATCH * NF2];         // ping
__device__ float2 g_buf2[BATCH * NF2];         // pong

// ---- packed f32x2 helpers (sm_103a FFMA2) ---------------------------------
__device__ __forceinline__ u64t pk2(float lo, float hi) {
    u64t r; asm("mov.b64 %0, {%1, %2};" : "=l"(r) : "f"(lo), "f"(hi)); return r;
}
__device__ __forceinline__ void fma2(u64t& d, u64t a, u64t b) {
    asm("fma.rn.f32x2 %0, %1, %2, %0;" : "+l"(d) : "l"(a), "l"(b));
}
__device__ __forceinline__ float2 unpk2(u64t v) {
    float lo, hi; asm("mov.b64 {%0, %1}, %2;" : "=f"(lo), "=f"(hi) : "l"(v));
    return make_float2(lo, hi);
}

// ---- complex helpers ------------------------------------------------------
__device__ __forceinline__ float2 cadd(float2 a, float2 b){ return make_float2(a.x+b.x, a.y+b.y); }
__device__ __forceinline__ float2 csub(float2 a, float2 b){ return make_float2(a.x-b.x, a.y-b.y); }
template<int DIR> __device__ __forceinline__ float2 mul_i(float2 a){
    return (DIR > 0) ? make_float2(a.y, -a.x) : make_float2(-a.y, a.x);
}
template<int DIR> __device__ __forceinline__ float2 ctw(float2 a, float2 tw){
    float ty = (DIR > 0) ? tw.y : -tw.y;
    return make_float2(fmaf(a.x,tw.x,-a.y*ty), fmaf(a.x,ty, a.y*tw.x));
}

// ---- radix-8 DFT (in place) -----------------------------------------------
template<int DIR> __device__ __forceinline__ void dft8(float2* a){
    float2 F0=cadd(a[0],a[4]), F1=csub(a[0],a[4]);
    float2 G0=cadd(a[2],a[6]), G1=csub(a[2],a[6]);
    float2 E0=cadd(F0,G0),     E2=csub(F0,G0);
    float2 G1i = mul_i<DIR>(G1);
    float2 E1=cadd(F1,G1i),    E3=csub(F1,G1i);

    float2 H0=cadd(a[1],a[5]), H1=csub(a[1],a[5]);
    float2 I0=cadd(a[3],a[7]), I1=csub(a[3],a[7]);
    float2 O0=cadd(H0,I0),     O2=csub(H0,I0);
    float2 I1i = mul_i<DIR>(I1);
    float2 O1=cadd(H1,I1i),    O3=csub(H1,I1i);

    const float s = 0.70710678118654752440f;
    float2 T1 = (DIR > 0) ? make_float2(s*(O1.x+O1.y), s*(O1.y-O1.x))
                          : make_float2(s*(O1.x-O1.y), s*(O1.y+O1.x));
    float2 T2 = mul_i<DIR>(O2);
    float2 T3 = (DIR > 0) ? make_float2(s*(O3.y-O3.x), -s*(O3.x+O3.y))
                          : make_float2(-s*(O3.x+O3.y), s*(O3.x-O3.y));

    a[0]=cadd(E0,O0); a[4]=csub(E0,O0);
    a[1]=cadd(E1,T1); a[5]=csub(E1,T1);
    a[2]=cadd(E2,T2); a[6]=csub(E2,T2);
    a[3]=cadd(E3,T3); a[7]=csub(E3,T3);
}

// ---------------------------------------------------------------------------
// Twiddles; also zero column 256 of Ttmp (row p=256 of T is identically zero,
// and mode 4's Hermitian dual-write never touches column 256).
// ---------------------------------------------------------------------------
__global__ void tw_kernel() {
    int k = blockIdx.x * blockDim.x + threadIdx.x;
    if (k >= NF) return;
    float sp, cp;
    sincospif((float)k / 256.0f, &sp, &cp);
    g_tw[k] = make_float2(cp, -sp);
    g_Ttmp[k * NF + 256] = make_float2(0.f, 0.f);
}

// ---------------------------------------------------------------------------
// ex/ey tables. Compute t in [0,255], mirror-write conj at (512-t)&511.
// Index 256 (offset +-256, never used) is zeroed.
// ---------------------------------------------------------------------------
__global__ void build_exp_kernel(const float* __restrict__ samples,
                                 const float* __restrict__ density) {
    int idx = blockIdx.x * blockDim.x + threadIdx.x;  // m*256 + t
    if (idx >= MSAMP * 256) return;
    int m = idx >> 8;
    int t = idx & 255;
    float p = (float)t;
    const float TWO_PI = 6.28318530717958647692f;
    float kx = samples[2*m], ky = samples[2*m+1];
    float sx, cx, sy, cy;
    sincosf(TWO_PI * kx * p, &sx, &cx);
    sincosf(TWO_PI * ky * p, &sy, &cy);
    float d = density[m] * (1.0f / 65536.0f);
    float2 exv = make_float2(cx * d, sx * d);
    float2 eyv = make_float2(cy, sy);
    g_ex[m * NF + t] = exv;
    g_ey[m * NF + t] = eyv;
    int tm = (NF - t) & (NF - 1);
    g_ex[m * NF + tm] = make_float2(exv.x, -exv.y);
    g_ey[m * NF + tm] = make_float2(eyv.x, -eyv.y);
    if (t == 0) {
        g_ex[m * NF + 256] = make_float2(0.f, 0.f);
        g_ey[m * NF + 256] = make_float2(0.f, 0.f);
    }
}

// ---------------------------------------------------------------------------
// T partials, Hermitian-halved: only p in [0,255] is computed/stored.
// (conj mirror is reconstructed in the mode-4 FFT via DFT symmetry.)
// 64x64 tile per CTA, FFMA2 inner loop.
// ---------------------------------------------------------------------------
__global__ __launch_bounds__(128, 4) void tpart_kernel() {
    __shared__ float2 sE[16 * 64]; // ex chunk [kk][p]
    __shared__ float2 sF[16 * 64]; // ey chunk [kk][q]

    int p0 = blockIdx.y * 64;      // 0..192
    int q0 = blockIdx.x * 64;
    int m0 = blockIdx.z * (MSAMP / KSPLIT);
    int tid = threadIdx.x;
    int ti = tid >> 4;   // 0..7
    int tj = tid & 15;   // 0..15

    u64t acc[8][4];
#pragma unroll
    for (int a = 0; a < 8; a++)
#pragma unroll
        for (int c = 0; c < 4; c++) acc[a][c] = 0ull;

    for (int k0 = 0; k0 < MSAMP / KSPLIT; k0 += 16) {
        __syncthreads();
#pragma unroll
        for (int u = tid; u < 1024; u += 128) {
            int kk  = u >> 6;
            int idx = u & 63;
            int m   = m0 + k0 + kk;
            sE[u] = g_ex[m * NF + p0 + idx];
            sF[u] = g_ey[m * NF + q0 + idx];
        }
        __syncthreads();

        const float4* sF4 = reinterpret_cast<const float4*>(sF);
#pragma unroll
        for (int kk = 0; kk < 16; ++kk) {
            int wbase = (kk * 64 + tj * 4) >> 1;
            float4 w01 = sF4[wbase];
            float4 w23 = sF4[wbase + 1];
            u64t W1[4], W2[4];
            W1[0] = pk2(w01.x, w01.x); W2[0] = pk2(-w01.y, w01.y);
            W1[1] = pk2(w01.z, w01.z); W2[1] = pk2(-w01.w, w01.w);
            W1[2] = pk2(w23.x, w23.x); W2[2] = pk2(-w23.y, w23.y);
            W1[3] = pk2(w23.z, w23.z); W2[3] = pk2(-w23.w, w23.w);
#pragma unroll
            for (int a = 0; a < 8; a++) {
                float2 av = sE[kk * 64 + ti + 8 * a];
                u64t avs = pk2(av.x, av.y);
                u64t avr = pk2(av.y, av.x);
#pragma unroll
                for (int c = 0; c < 4; c++) {
                    fma2(acc[a][c], W1[c], avs);
                    fma2(acc[a][c], W2[c], avr);
                }
            }
        }
    }

    float2* outp = g_Tpart + blockIdx.z * (256 * NF);
#pragma unroll
    for (int a = 0; a < 8; a++) {
        int p = p0 + ti + 8 * a;              // 0..255
#pragma unroll
        for (int c = 0; c < 4; c++) {
            int q = q0 + tj * 4 + c;
            outp[p * NF + q] = unpk2(acc[a][c]);
        }
    }
}

// ---------------------------------------------------------------------------
// Generic 512-pt Stockham radix-8 FFT pass. 64 threads/line, 8 lines/CTA
// (512 threads). Output staged through smem, written as coalesced bursts
// along the line axis.
// MODE 0: x fwd pass1 (zero-pad load from xr/xi rows), -> buf1[v][i]
// MODE 1: x fwd pass2 (zero-pad load buf1[v][*]),      -> buf2[u][v]
// MODE 2: x inv pass1 (load buf2[u][*] * TFr[u][*]),   -> buf1[j][u], j<256
// MODE 3: x inv pass2 (load buf1[j][*]),               -> out[i][j], i<256, /512^2
// MODE 4: T pass1, p in [0,255] (treduce fused into load); Hermitian dual
//         write: Ttmp[v][p] and Ttmp[v][512-p] = conj  (32 CTAs)
// MODE 5: T pass2 (load Ttmp[v][*]), real output       -> TFr[u][v] (float)
// ---------------------------------------------------------------------------
#define SPAD(x) ((x) + ((x) >> 3))
#define TSTRIDE 514   // transpose-stage line stride: conflict-free burst reads

template<int MODE, int DIR>
__global__ __launch_bounds__(512) void fft_pass_kernel(
    const float* __restrict__ xr, const float* __restrict__ xi,
    float2* __restrict__ out)
{
    __shared__ float2 s_tw[NF];
    __shared__ float2 s_buf[8][576];
    float2* sTr = &s_buf[0][0];    // reused as sT[line][k], stride TSTRIDE

    int t = threadIdx.x;
    int grp = t >> 6;          // line within CTA (0..7)
    int i   = t & 63;          // butterfly index

    s_tw[t] = g_tw[t];

    int line = blockIdx.x * 8 + grp;

    // ---- decode line, load 8 inputs: a[r] = in[i + 64r] ----
    float2 a[8];
    int b = 0, l2 = 0;
    if (MODE == 0) {
        b = line >> 8; l2 = line & 255;                 // l2 = image row i
        const float* pr = xr + ((b << 16) + (l2 << 8));
        const float* pi = xi + ((b << 16) + (l2 << 8));
#pragma unroll
        for (int r = 0; r < 8; r++) {
            if (r < 4) { int n = i + (r << 6); a[r] = make_float2(pr[n], pi[n]); }
            else a[r] = make_float2(0.f, 0.f);
        }
    } else if (MODE == 1) {
        b = line >> 9; l2 = line & 511;                 // l2 = v
        const float2* src = g_buf1 + b * NF2 + l2 * NF;
#pragma unroll
        for (int r = 0; r < 8; r++)
            a[r] = (r < 4) ? src[i + (r << 6)] : make_float2(0.f, 0.f);
    } else if (MODE == 2) {
        b = line >> 9; l2 = line & 511;                 // l2 = u
        const float2* src = g_buf2 + b * NF2 + l2 * NF;
        const float* tf   = g_TFr + l2 * NF;            // TFr[u][v] (real)
#pragma unroll
        for (int r = 0; r < 8; r++) {
            int n = i + (r << 6);
            float2 v = src[n];
            float  s = tf[n];
            a[r] = make_float2(v.x * s, v.y * s);
        }
    } else if (MODE == 3) {
        b = line >> 8; l2 = line & 255;                 // l2 = j
        const float2* src = g_buf1 + b * NF2 + l2 * NF;
#pragma unroll
        for (int r = 0; r < 8; r++) a[r] = src[i + (r << 6)];
    } else if (MODE == 4) {
        l2 = line;                                      // l2 = p in [0,255]
        const float2* src = g_Tpart + l2 * NF;
#pragma unroll
        for (int r = 0; r < 8; r++) {
            float2 s = make_float2(0.f, 0.f);
#pragma unroll
            for (int z = 0; z < KSPLIT; z++)
                s = cadd(s, src[z * (256 * NF) + i + (r << 6)]);
            a[r] = s;
        }
    } else { // MODE 5
        l2 = line;                                      // l2 = v
        const float2* src = g_Ttmp + l2 * NF;
#pragma unroll
        for (int r = 0; r < 8; r++) a[r] = src[i + (r << 6)];
    }

    // ---- stage 0 (L=1) ----
    dft8<DIR>(a);
#pragma unroll
    for (int r = 0; r < 8; r++) s_buf[grp][SPAD(8 * i + r)] = a[r];
    __syncthreads();

    // ---- stage 1 (L=8): twiddle W512^{8*p*r}, p = i&7 ----
#pragma unroll
    for (int r = 0; r < 8; r++) a[r] = s_buf[grp][SPAD(i + 64 * r)];
    {
        int p = i & 7;
#pragma unroll
        for (int r = 1; r < 8; r++) a[r] = ctw<DIR>(a[r], s_tw[(p * r) << 3]);
    }
    dft8<DIR>(a);
    __syncthreads();
#pragma unroll
    for (int r = 0; r < 8; r++)
        s_buf[grp][SPAD(((i >> 3) << 6) + (r << 3) + (i & 7))] = a[r];
    __syncthreads();

    // ---- stage 2 (L=64): twiddle W512^{i*r} ----
#pragma unroll
    for (int r = 0; r < 8; r++) a[r] = s_buf[grp][SPAD(i + 64 * r)];
#pragma unroll
    for (int r = 1; r < 8; r++) a[r] = ctw<DIR>(a[r], s_tw[i * r]);
    dft8<DIR>(a);

    // ---- transpose through smem: sT[grp][k], k = r*64 + i ----
    __syncthreads();   // all stage-2 reads of s_buf complete
#pragma unroll
    for (int r = 0; r < 8; r++) sTr[grp * TSTRIDE + ((r << 6) + i)] = a[r];
    __syncthreads();

    if (MODE == 4) {
        // Hermitian dual write: Ttmp[k][p] straight, Ttmp[k][512-p] = conj.
        int l2b = blockIdx.x * 8;                       // 0..248
#pragma unroll
        for (int w = 0; w < 4; w++) {
            int idx = w * 512 + t;
            int k   = idx >> 2;
            int gp  = idx & 3;
            float2 v0 = sTr[(2 * gp)     * TSTRIDE + k];
            float2 v1 = sTr[(2 * gp + 1) * TSTRIDE + k];
            int c0 = l2b + 2 * gp;
            float4* p4 = reinterpret_cast<float4*>(g_Ttmp + k * NF + c0);
            *p4 = make_float4(v0.x, v0.y, v1.x, v1.y);
            if (c0 > 0) {
                g_Ttmp[k * NF + (NF - c0)]     = make_float2(v0.x, -v0.y);
                g_Ttmp[k * NF + (NF - c0 - 1)] = make_float2(v1.x, -v1.y);
            } else {
                g_Ttmp[k * NF + (NF - 1)]      = make_float2(v1.x, -v1.y);
            }
        }
        return;
    }
    if (MODE == 5) {
        // Real output: TFr[u][v] as float.
        int l2b = blockIdx.x * 8;
#pragma unroll
        for (int w = 0; w < 4; w++) {
            int idx = w * 512 + t;
            int k   = idx >> 2;
            int gp  = idx & 3;
            float r0 = sTr[(2 * gp)     * TSTRIDE + k].x;
            float r1 = sTr[(2 * gp + 1) * TSTRIDE + k].x;
            float2* p2 = reinterpret_cast<float2*>(g_TFr + k * NF + l2b + 2 * gp);
            *p2 = make_float2(r0, r1);
        }
        return;
    }

    // ---- coalesced output: float4 bursts along the line (l2) axis ----
    const int KMAX  = (MODE == 2 || MODE == 3) ? 256 : 512;
    const int l2b   = (MODE == 0 || MODE == 3) ? ((blockIdx.x * 8) & 255)
                                               : ((blockIdx.x * 8) & 511);
    float2* dst;
    int rowstride;
    if (MODE == 0)      { dst = g_buf1 + b * NF2; rowstride = NF;  }
    else if (MODE == 1) { dst = g_buf2 + b * NF2; rowstride = NF;  }
    else if (MODE == 2) { dst = g_buf1 + b * NF2; rowstride = NF;  }
    else                { dst = out + (b << 16);  rowstride = 256; }

#pragma unroll
    for (int w = 0; w < KMAX / 128; w++) {
        int idx = w * 512 + t;
        int k   = idx >> 2;
        int gp  = idx & 3;
        float2 v0 = sTr[(2 * gp)     * TSTRIDE + k];
        float2 v1 = sTr[(2 * gp + 1) * TSTRIDE + k];
        if (MODE == 3) {
            const float s = 1.0f / 262144.0f;
            v0.x *= s; v0.y *= s; v1.x *= s; v1.y *= s;
        }
        float4* p4 = reinterpret_cast<float4*>(dst + k * rowstride + l2b + 2 * gp);
        *p4 = make_float4(v0.x, v0.y, v1.x, v1.y);
    }
}

// ---------------------------------------------------------------------------
extern "C" void kernel_launch(void* const* d_in, const int* in_sizes, int n_in,
                              void* d_out, int out_size)
{
    const float* xr      = (const float*)d_in[0];
    const float* xi      = (const float*)d_in[1];
    const float* samples = (const float*)d_in[2];
    const float* density = (const float*)d_in[3];
    float2* out = (float2*)d_out;

    tw_kernel<<<2, 256>>>();
    build_exp_kernel<<<MSAMP, 256>>>(samples, density);
    tpart_kernel<<<dim3(8, 4, KSPLIT), 128>>>();

    // FFT2 of Toeplitz kernel (treduce fused into MODE 4 load; Hermitian halved)
    fft_pass_kernel<4, 1><<<256 / 8, 512>>>(nullptr, nullptr, nullptr);
    fft_pass_kernel<5, 1><<<NF / 8, 512>>>(nullptr, nullptr, nullptr);

    // x: forward FFT2 (zero-padded), pointwise real TF (in MODE 2 load),
    // inverse FFT2, crop + scale
    fft_pass_kernel<0, 1><<<BATCH * 256 / 8, 512>>>(xr, xi, nullptr);
    fft_pass_kernel<1, 1><<<BATCH * 512 / 8, 512>>>(nullptr, nullptr, nullptr);
    fft_pass_kernel<2, -1><<<BATCH * 512 / 8, 512>>>(nullptr, nullptr, nullptr);
    fft_pass_kernel<3, -1><<<BATCH * 256 / 8, 512>>>(nullptr, nullptr, out);
}

// round 14
// speedup vs baseline: 1.1350x; 1.1350x over previous
#include <cuda_runtime.h>

#define IMG 256
#define MSAMP 1920
#define BATCH 64
#define NF 512                 // FFT size
#define NF2 (NF*NF)            // 262144
#define KSPLIT 12              // T-build K partitions (1920 = 12*160)

typedef unsigned long long u64t;

// ---------------------------------------------------------------------------
// Device scratch (static globals; no runtime allocation allowed)
// ---------------------------------------------------------------------------
__device__ float2 g_ex[MSAMP * NF];            // d_m/65536 * exp(+2i pi kx_m p)
__device__ float2 g_ey[MSAMP * NF];            // exp(+2i pi ky_m q)
__device__ float2 g_Tpart[KSPLIT * 256 * NF];  // K-split partials, p in [0,255] only
__device__ float2 g_Ttmp[NF2];                 // T after row FFT: [v][p]
__device__ float  g_TFr[NF2];                  // FFT2(T) (real!), stored [u][v]
__device__ float2 g_tw[NF];                    // W512^k = exp(-2i pi k/512)
__device__ float2 g_buf1[BATCH * NF2];         // ping
__device__ float2 g_buf2[BATCH * NF2];         // pong

// ---- packed f32x2 helpers (sm_103a FFMA2) ---------------------------------
__device__ __forceinline__ u64t pk2(float lo, float hi) {
    u64t r; asm("mov.b64 %0, {%1, %2};" : "=l"(r) : "f"(lo), "f"(hi)); return r;
}
__device__ __forceinline__ void fma2(u64t& d, u64t a, u64t b) {
    asm("fma.rn.f32x2 %0, %1, %2, %0;" : "+l"(d) : "l"(a), "l"(b));
}
__device__ __forceinline__ float2 unpk2(u64t v) {
    float lo, hi; asm("mov.b64 {%0, %1}, %2;" : "=f"(lo), "=f"(hi) : "l"(v));
    return make_float2(lo, hi);
}

// ---- complex helpers ------------------------------------------------------
__device__ __forceinline__ float2 cadd(float2 a, float2 b){ return make_float2(a.x+b.x, a.y+b.y); }
__device__ __forceinline__ float2 csub(float2 a, float2 b){ return make_float2(a.x-b.x, a.y-b.y); }
template<int DIR> __device__ __forceinline__ float2 mul_i(float2 a){
    return (DIR > 0) ? make_float2(a.y, -a.x) : make_float2(-a.y, a.x);
}
template<int DIR> __device__ __forceinline__ float2 ctw(float2 a, float2 tw){
    float ty = (DIR > 0) ? tw.y : -tw.y;
    return make_float2(fmaf(a.x,tw.x,-a.y*ty), fmaf(a.x,ty, a.y*tw.x));
}

// ---- radix-8 DFT (in place) -----------------------------------------------
template<int DIR> __device__ __forceinline__ void dft8(float2* a){
    float2 F0=cadd(a[0],a[4]), F1=csub(a[0],a[4]);
    float2 G0=cadd(a[2],a[6]), G1=csub(a[2],a[6]);
    float2 E0=cadd(F0,G0),     E2=csub(F0,G0);
    float2 G1i = mul_i<DIR>(G1);
    float2 E1=cadd(F1,G1i),    E3=csub(F1,G1i);

    float2 H0=cadd(a[1],a[5]), H1=csub(a[1],a[5]);
    float2 I0=cadd(a[3],a[7]), I1=csub(a[3],a[7]);
    float2 O0=cadd(H0,I0),     O2=csub(H0,I0);
    float2 I1i = mul_i<DIR>(I1);
    float2 O1=cadd(H1,I1i),    O3=csub(H1,I1i);

    const float s = 0.70710678118654752440f;
    float2 T1 = (DIR > 0) ? make_float2(s*(O1.x+O1.y), s*(O1.y-O1.x))
                          : make_float2(s*(O1.x-O1.y), s*(O1.y+O1.x));
    float2 T2 = mul_i<DIR>(O2);
    float2 T3 = (DIR > 0) ? make_float2(s*(O3.y-O3.x), -s*(O3.x+O3.y))
                          : make_float2(-s*(O3.x+O3.y), s*(O3.x-O3.y));

    a[0]=cadd(E0,O0); a[4]=csub(E0,O0);
    a[1]=cadd(E1,T1); a[5]=csub(E1,T1);
    a[2]=cadd(E2,T2); a[6]=csub(E2,T2);
    a[3]=cadd(E3,T3); a[7]=csub(E3,T3);
}

// ---------------------------------------------------------------------------
// Twiddles; also zero column 256 of Ttmp (row p=256 of T is identically zero,
// and mode 4's Hermitian dual-write never touches column 256).
// ---------------------------------------------------------------------------
__global__ void tw_kernel() {
    int k = blockIdx.x * blockDim.x + threadIdx.x;
    if (k >= NF) return;
    float sp, cp;
    sincospif((float)k / 256.0f, &sp, &cp);
    g_tw[k] = make_float2(cp, -sp);
    g_Ttmp[k * NF + 256] = make_float2(0.f, 0.f);
}

// ---------------------------------------------------------------------------
// ex/ey tables. Compute t in [0,255], mirror-write conj at (512-t)&511.
// Index 256 (offset +-256, never used) is zeroed.
// ---------------------------------------------------------------------------
__global__ void build_exp_kernel(const float* __restrict__ samples,
                                 const float* __restrict__ density) {
    int idx = blockIdx.x * blockDim.x + threadIdx.x;  // m*256 + t
    if (idx >= MSAMP * 256) return;
    int m = idx >> 8;
    int t = idx & 255;
    float p = (float)t;
    const float TWO_PI = 6.28318530717958647692f;
    float kx = samples[2*m], ky = samples[2*m+1];
    float sx, cx, sy, cy;
    sincosf(TWO_PI * kx * p, &sx, &cx);
    sincosf(TWO_PI * ky * p, &sy, &cy);
    float d = density[m] * (1.0f / 65536.0f);
    float2 exv = make_float2(cx * d, sx * d);
    float2 eyv = make_float2(cy, sy);
    g_ex[m * NF + t] = exv;
    g_ey[m * NF + t] = eyv;
    int tm = (NF - t) & (NF - 1);
    g_ex[m * NF + tm] = make_float2(exv.x, -exv.y);
    g_ey[m * NF + tm] = make_float2(eyv.x, -eyv.y);
    if (t == 0) {
        g_ex[m * NF + 256] = make_float2(0.f, 0.f);
        g_ey[m * NF + 256] = make_float2(0.f, 0.f);
    }
}

// ---------------------------------------------------------------------------
// T partials, Hermitian-halved: only p in [0,255] is computed/stored.
// (conj mirror is reconstructed in the mode-4 FFT via DFT symmetry.)
// 64x64 tile per CTA, FFMA2 inner loop.
// ---------------------------------------------------------------------------
__global__ __launch_bounds__(128, 4) void tpart_kernel() {
    __shared__ float2 sE[16 * 64]; // ex chunk [kk][p]
    __shared__ float2 sF[16 * 64]; // ey chunk [kk][q]

    int p0 = blockIdx.y * 64;      // 0..192
    int q0 = blockIdx.x * 64;
    int m0 = blockIdx.z * (MSAMP / KSPLIT);
    int tid = threadIdx.x;
    int ti = tid >> 4;   // 0..7
    int tj = tid & 15;   // 0..15

    u64t acc[8][4];
#pragma unroll
    for (int a = 0; a < 8; a++)
#pragma unroll
        for (int c = 0; c < 4; c++) acc[a][c] = 0ull;

    for (int k0 = 0; k0 < MSAMP / KSPLIT; k0 += 16) {
        __syncthreads();
#pragma unroll
        for (int u = tid; u < 1024; u += 128) {
            int kk  = u >> 6;
            int idx = u & 63;
            int m   = m0 + k0 + kk;
            sE[u] = g_ex[m * NF + p0 + idx];
            sF[u] = g_ey[m * NF + q0 + idx];
        }
        __syncthreads();

        const float4* sF4 = reinterpret_cast<const float4*>(sF);
#pragma unroll
        for (int kk = 0; kk < 16; ++kk) {
            int wbase = (kk * 64 + tj * 4) >> 1;
            float4 w01 = sF4[wbase];
            float4 w23 = sF4[wbase + 1];
            u64t W1[4], W2[4];
            W1[0] = pk2(w01.x, w01.x); W2[0] = pk2(-w01.y, w01.y);
            W1[1] = pk2(w01.z, w01.z); W2[1] = pk2(-w01.w, w01.w);
            W1[2] = pk2(w23.x, w23.x); W2[2] = pk2(-w23.y, w23.y);
            W1[3] = pk2(w23.z, w23.z); W2[3] = pk2(-w23.w, w23.w);
#pragma unroll
            for (int a = 0; a < 8; a++) {
                float2 av = sE[kk * 64 + ti + 8 * a];
                u64t avs = pk2(av.x, av.y);
                u64t avr = pk2(av.y, av.x);
#pragma unroll
                for (int c = 0; c < 4; c++) {
                    fma2(acc[a][c], W1[c], avs);
                    fma2(acc[a][c], W2[c], avr);
                }
            }
        }
    }

    float2* outp = g_Tpart + blockIdx.z * (256 * NF);
#pragma unroll
    for (int a = 0; a < 8; a++) {
        int p = p0 + ti + 8 * a;              // 0..255
#pragma unroll
        for (int c = 0; c < 4; c++) {
            int q = q0 + tj * 4 + c;
            outp[p * NF + q] = unpk2(acc[a][c]);
        }
    }
}

// ---------------------------------------------------------------------------
// Generic 512-pt Stockham radix-8 FFT pass. 64 threads/line, 8 lines/CTA
// (512 threads). Output staged through smem, written as coalesced bursts
// along the line axis.
// MODE 0: x fwd pass1 (zero-pad load from xr/xi rows), -> buf1[v][i]
// MODE 1: x fwd pass2 (zero-pad load buf1[v][*]),      -> buf2[u][v]
// MODE 2: x inv pass1 (load buf2[u][*] * TFr[u][*]),   -> buf1[j][u], j<256
// MODE 3: x inv pass2 (load buf1[j][*]),               -> out[i][j], i<256, /512^2
// MODE 4: T pass1, p in [0,255] (treduce fused into load); Hermitian dual
//         write: Ttmp[v][p] and Ttmp[v][512-p] = conj  (32 CTAs)
// MODE 5: T pass2 (load Ttmp[v][*]), real output       -> TFr[u][v] (float)
// ---------------------------------------------------------------------------
#define SPAD(x) ((x) + ((x) >> 3))
#define TSTRIDE 514   // transpose-stage line stride: conflict-free burst reads

template<int MODE, int DIR>
__global__ __launch_bounds__(512) void fft_pass_kernel(
    const float* __restrict__ xr, const float* __restrict__ xi,
    float2* __restrict__ out)
{
    __shared__ float2 s_tw[NF];
    __shared__ float2 s_buf[8][576];
    float2* sTr = &s_buf[0][0];    // reused as sT[line][k], stride TSTRIDE

    int t = threadIdx.x;
    int grp = t >> 6;          // line within CTA (0..7)
    int i   = t & 63;          // butterfly index

    s_tw[t] = g_tw[t];

    int line = blockIdx.x * 8 + grp;

    // ---- decode line, load 8 inputs: a[r] = in[i + 64r] ----
    float2 a[8];
    int b = 0, l2 = 0;
    if (MODE == 0) {
        b = line >> 8; l2 = line & 255;                 // l2 = image row i
        const float* pr = xr + ((b << 16) + (l2 << 8));
        const float* pi = xi + ((b << 16) + (l2 << 8));
#pragma unroll
        for (int r = 0; r < 8; r++) {
            if (r < 4) { int n = i + (r << 6); a[r] = make_float2(pr[n], pi[n]); }
            else a[r] = make_float2(0.f, 0.f);
        }
    } else if (MODE == 1) {
        b = line >> 9; l2 = line & 511;                 // l2 = v
        const float2* src = g_buf1 + b * NF2 + l2 * NF;
#pragma unroll
        for (int r = 0; r < 8; r++)
            a[r] = (r < 4) ? src[i + (r << 6)] : make_float2(0.f, 0.f);
    } else if (MODE == 2) {
        b = line >> 9; l2 = line & 511;                 // l2 = u
        const float2* src = g_buf2 + b * NF2 + l2 * NF;
        const float* tf   = g_TFr + l2 * NF;            // TFr[u][v] (real)
#pragma unroll
        for (int r = 0; r < 8; r++) {
            int n = i + (r << 6);
            float2 v = src[n];
            float  s = tf[n];
            a[r] = make_float2(v.x * s, v.y * s);
        }
    } else if (MODE == 3) {
        b = line >> 8; l2 = line & 255;                 // l2 = j
        const float2* src = g_buf1 + b * NF2 + l2 * NF;
#pragma unroll
        for (int r = 0; r < 8; r++) a[r] = src[i + (r << 6)];
    } else if (MODE == 4) {
        l2 = line;                                      // l2 = p in [0,255]
        const float2* src = g_Tpart + l2 * NF;
#pragma unroll
        for (int r = 0; r < 8; r++) {
            float2 s = make_float2(0.f, 0.f);
#pragma unroll
            for (int z = 0; z < KSPLIT; z++)
                s = cadd(s, src[z * (256 * NF) + i + (r << 6)]);
            a[r] = s;
        }
    } else { // MODE 5
        l2 = line;                                      // l2 = v
        const float2* src = g_Ttmp + l2 * NF;
#pragma unroll
        for (int r = 0; r < 8; r++) a[r] = src[i + (r << 6)];
    }

    // ---- stage 0 (L=1) ----
    dft8<DIR>(a);
#pragma unroll
    for (int r = 0; r < 8; r++) s_buf[grp][SPAD(8 * i + r)] = a[r];
    __syncthreads();

    // ---- stage 1 (L=8): twiddle W512^{8*p*r}, p = i&7 ----
#pragma unroll
    for (int r = 0; r < 8; r++) a[r] = s_buf[grp][SPAD(i + 64 * r)];
    {
        int p = i & 7;
#pragma unroll
        for (int r = 1; r < 8; r++) a[r] = ctw<DIR>(a[r], s_tw[(p * r) << 3]);
    }
    dft8<DIR>(a);
    __syncthreads();
#pragma unroll
    for (int r = 0; r < 8; r++)
        s_buf[grp][SPAD(((i >> 3) << 6) + (r << 3) + (i & 7))] = a[r];
    __syncthreads();

    // ---- stage 2 (L=64): twiddle W512^{i*r} ----
#pragma unroll
    for (int r = 0; r < 8; r++) a[r] = s_buf[grp][SPAD(i + 64 * r)];
#pragma unroll
    for (int r = 1; r < 8; r++) a[r] = ctw<DIR>(a[r], s_tw[i * r]);
    dft8<DIR>(a);

    // ---- transpose through smem: sT[grp][k], k = r*64 + i ----
    __syncthreads();   // all stage-2 reads of s_buf complete
#pragma unroll
    for (int r = 0; r < 8; r++) sTr[grp * TSTRIDE + ((r << 6) + i)] = a[r];
    __syncthreads();

    if (MODE == 4) {
        // Hermitian dual write: Ttmp[k][p] straight, Ttmp[k][512-p] = conj.
        int l2b = blockIdx.x * 8;                       // 0..248
#pragma unroll
        for (int w = 0; w < 4; w++) {
            int idx = w * 512 + t;
            int k   = idx >> 2;
            int gp  = idx & 3;
            float2 v0 = sTr[(2 * gp)     * TSTRIDE + k];
            float2 v1 = sTr[(2 * gp + 1) * TSTRIDE + k];
            int c0 = l2b + 2 * gp;
            float4* p4 = reinterpret_cast<float4*>(g_Ttmp + k * NF + c0);
            *p4 = make_float4(v0.x, v0.y, v1.x, v1.y);
            if (c0 > 0) {
                g_Ttmp[k * NF + (NF - c0)]     = make_float2(v0.x, -v0.y);
                g_Ttmp[k * NF + (NF - c0 - 1)] = make_float2(v1.x, -v1.y);
            } else {
                g_Ttmp[k * NF + (NF - 1)]      = make_float2(v1.x, -v1.y);
            }
        }
        return;
    }
    if (MODE == 5) {
        // Real output: TFr[u][v] as float.
        int l2b = blockIdx.x * 8;
#pragma unroll
        for (int w = 0; w < 4; w++) {
            int idx = w * 512 + t;
            int k   = idx >> 2;
            int gp  = idx & 3;
            float r0 = sTr[(2 * gp)     * TSTRIDE + k].x;
            float r1 = sTr[(2 * gp + 1) * TSTRIDE + k].x;
            float2* p2 = reinterpret_cast<float2*>(g_TFr + k * NF + l2b + 2 * gp);
            *p2 = make_float2(r0, r1);
        }
        return;
    }

    // ---- coalesced output: float4 bursts along the line (l2) axis ----
    const int KMAX  = (MODE == 2 || MODE == 3) ? 256 : 512;
    const int l2b   = (MODE == 0 || MODE == 3) ? ((blockIdx.x * 8) & 255)
                                               : ((blockIdx.x * 8) & 511);
    float2* dst;
    int rowstride;
    if (MODE == 0)      { dst = g_buf1 + b * NF2; rowstride = NF;  }
    else if (MODE == 1) { dst = g_buf2 + b * NF2; rowstride = NF;  }
    else if (MODE == 2) { dst = g_buf1 + b * NF2; rowstride = NF;  }
    else                { dst = out + (b << 16);  rowstride = 256; }

#pragma unroll
    for (int w = 0; w < KMAX / 128; w++) {
        int idx = w * 512 + t;
        int k   = idx >> 2;
        int gp  = idx & 3;
        float2 v0 = sTr[(2 * gp)     * TSTRIDE + k];
        float2 v1 = sTr[(2 * gp + 1) * TSTRIDE + k];
        if (MODE == 3) {
            const float s = 1.0f / 262144.0f;
            v0.x *= s; v0.y *= s; v1.x *= s; v1.y *= s;
        }
        float4* p4 = reinterpret_cast<float4*>(dst + k * rowstride + l2b + 2 * gp);
        *p4 = make_float4(v0.x, v0.y, v1.x, v1.y);
    }
}

// ---------------------------------------------------------------------------
// Launch graph:
//   branch A (default stream): mode0 -> mode1            (x-chain head)
//   branch B (s2, forked):     tw -> build_exp -> tpart -> mode4 -> mode5
//   join, then mode2 -> mode3 on default stream.
// Stream/events are host-side handles created ONCE on the first call (the
// eager correctness run) so that no creation APIs execute during graph
// capture; every call then records the identical fork/join launch topology
// (same inputs -> same work -> same output).
// ---------------------------------------------------------------------------
extern "C" void kernel_launch(void* const* d_in, const int* in_sizes, int n_in,
                              void* d_out, int out_size)
{
    const float* xr      = (const float*)d_in[0];
    const float* xi      = (const float*)d_in[1];
    const float* samples = (const float*)d_in[2];
    const float* density = (const float*)d_in[3];
    float2* out = (float2*)d_out;

    struct ForkCtx {
        cudaStream_t s2;
        cudaEvent_t evFork, evJoin;
        ForkCtx() {
            cudaStreamCreateWithFlags(&s2, cudaStreamNonBlocking);
            cudaEventCreateWithFlags(&evFork, cudaEventDisableTiming);
            cudaEventCreateWithFlags(&evJoin, cudaEventDisableTiming);
        }
    };
    static ForkCtx ctx;   // created on first (eager) call; reused every call

    // Fork s2 off the (possibly capturing) default stream.
    cudaEventRecord(ctx.evFork, 0);
    cudaStreamWaitEvent(ctx.s2, ctx.evFork, 0);

    // ---- branch B: Toeplitz kernel chain on s2 ----
    tw_kernel<<<2, 256, 0, ctx.s2>>>();
    build_exp_kernel<<<MSAMP, 256, 0, ctx.s2>>>(samples, density);
    tpart_kernel<<<dim3(8, 4, KSPLIT), 128, 0, ctx.s2>>>();
    fft_pass_kernel<4, 1><<<256 / 8, 512, 0, ctx.s2>>>(nullptr, nullptr, nullptr);
    fft_pass_kernel<5, 1><<<NF / 8, 512, 0, ctx.s2>>>(nullptr, nullptr, nullptr);

    // ---- branch A: x forward FFT2 on default stream ----
    fft_pass_kernel<0, 1><<<BATCH * 256 / 8, 512>>>(xr, xi, nullptr);
    fft_pass_kernel<1, 1><<<BATCH * 512 / 8, 512>>>(nullptr, nullptr, nullptr);

    // Join: default stream waits for branch B (TFr ready).
    cudaEventRecord(ctx.evJoin, ctx.s2);
    cudaStreamWaitEvent(0, ctx.evJoin, 0);

    // ---- tail: pointwise real TF (in MODE 2 load), inverse FFT2, crop ----
    fft_pass_kernel<2, -1><<<BATCH * 512 / 8, 512>>>(nullptr, nullptr, nullptr);
    fft_pass_kernel<3, -1><<<BATCH * 256 / 8, 512>>>(nullptr, nullptr, out);
}

// round 17
// speedup vs baseline: 1.1592x; 1.0213x over previous
#include <cuda_runtime.h>

#define IMG 256
#define MSAMP 1920
#define BATCH 64
#define NF 512                 // FFT size
#define NF2 (NF*NF)            // 262144
#define KSPLIT 12              // T-build K partitions (1920 = 12*160)

typedef unsigned long long u64t;

// ---------------------------------------------------------------------------
// Device scratch (static globals; no runtime allocation allowed)
// ---------------------------------------------------------------------------
__device__ float2 g_ex[MSAMP * NF];            // d_m/65536 * exp(+2i pi kx_m p)
__device__ float2 g_ey[MSAMP * NF];            // exp(+2i pi ky_m q)
__device__ float2 g_Tpart[KSPLIT * 256 * NF];  // K-split partials, p in [0,255] only
__device__ float2 g_Ttmp[NF2];                 // T after row FFT: [v][p]
__device__ float  g_TFr[NF2];                  // FFT2(T) (real!), stored [v][u]
__device__ float2 g_tw[NF];                    // W512^k = exp(-2i pi k/512)
__device__ float2 g_buf1[BATCH * NF2];         // [v][i<256]
__device__ float2 g_buf2[BATCH * NF2];         // [i<256][v]

// ---- packed f32x2 helpers (sm_103a FFMA2) ---------------------------------
__device__ __forceinline__ u64t pk2(float lo, float hi) {
    u64t r; asm("mov.b64 %0, {%1, %2};" : "=l"(r) : "f"(lo), "f"(hi)); return r;
}
__device__ __forceinline__ void fma2(u64t& d, u64t a, u64t b) {
    asm("fma.rn.f32x2 %0, %1, %2, %0;" : "+l"(d) : "l"(a), "l"(b));
}
__device__ __forceinline__ float2 unpk2(u64t v) {
    float lo, hi; asm("mov.b64 {%0, %1}, %2;" : "=f"(lo), "=f"(hi) : "l"(v));
    return make_float2(lo, hi);
}

// ---- complex helpers ------------------------------------------------------
__device__ __forceinline__ float2 cadd(float2 a, float2 b){ return make_float2(a.x+b.x, a.y+b.y); }
__device__ __forceinline__ float2 csub(float2 a, float2 b){ return make_float2(a.x-b.x, a.y-b.y); }
template<int DIR> __device__ __forceinline__ float2 mul_i(float2 a){
    return (DIR > 0) ? make_float2(a.y, -a.x) : make_float2(-a.y, a.x);
}
template<int DIR> __device__ __forceinline__ float2 ctw(float2 a, float2 tw){
    float ty = (DIR > 0) ? tw.y : -tw.y;
    return make_float2(fmaf(a.x,tw.x,-a.y*ty), fmaf(a.x,ty, a.y*tw.x));
}

// ---- radix-8 DFT (in place) -----------------------------------------------
template<int DIR> __device__ __forceinline__ void dft8(float2* a){
    float2 F0=cadd(a[0],a[4]), F1=csub(a[0],a[4]);
    float2 G0=cadd(a[2],a[6]), G1=csub(a[2],a[6]);
    float2 E0=cadd(F0,G0),     E2=csub(F0,G0);
    float2 G1i = mul_i<DIR>(G1);
    float2 E1=cadd(F1,G1i),    E3=csub(F1,G1i);

    float2 H0=cadd(a[1],a[5]), H1=csub(a[1],a[5]);
    float2 I0=cadd(a[3],a[7]), I1=csub(a[3],a[7]);
    float2 O0=cadd(H0,I0),     O2=csub(H0,I0);
    float2 I1i = mul_i<DIR>(I1);
    float2 O1=cadd(H1,I1i),    O3=csub(H1,I1i);

    const float s = 0.70710678118654752440f;
    float2 T1 = (DIR > 0) ? make_float2(s*(O1.x+O1.y), s*(O1.y-O1.x))
                          : make_float2(s*(O1.x-O1.y), s*(O1.y+O1.x));
    float2 T2 = mul_i<DIR>(O2);
    float2 T3 = (DIR > 0) ? make_float2(s*(O3.y-O3.x), -s*(O3.x+O3.y))
                          : make_float2(-s*(O3.x+O3.y), s*(O3.x-O3.y));

    a[0]=cadd(E0,O0); a[4]=csub(E0,O0);
    a[1]=cadd(E1,T1); a[5]=csub(E1,T1);
    a[2]=cadd(E2,T2); a[6]=csub(E2,T2);
    a[3]=cadd(E3,T3); a[7]=csub(E3,T3);
}

#define SPAD(x) ((x) + ((x) >> 3))
#define TSTRIDE 514   // transpose-stage line stride: conflict-free burst reads

// ---- 512-pt Stockham radix-8, 3 stages. Input a[r]=in[i+64r]; output
// a[r]=OUT[r*64+i]. Uses per-line smem region sline (SPAD addressing).
// CTA-wide __syncthreads inside; all threads must call uniformly.
template<int DIR>
__device__ __forceinline__ void fft512_stages(float2* a, float2* sline,
                                              const float2* s_tw, int i)
{
    dft8<DIR>(a);
#pragma unroll
    for (int r = 0; r < 8; r++) sline[SPAD(8 * i + r)] = a[r];
    __syncthreads();
#pragma unroll
    for (int r = 0; r < 8; r++) a[r] = sline[SPAD(i + 64 * r)];
    {
        int p = i & 7;
#pragma unroll
        for (int r = 1; r < 8; r++) a[r] = ctw<DIR>(a[r], s_tw[(p * r) << 3]);
    }
    dft8<DIR>(a);
    __syncthreads();
#pragma unroll
    for (int r = 0; r < 8; r++)
        sline[SPAD(((i >> 3) << 6) + (r << 3) + (i & 7))] = a[r];
    __syncthreads();
#pragma unroll
    for (int r = 0; r < 8; r++) a[r] = sline[SPAD(i + 64 * r)];
#pragma unroll
    for (int r = 1; r < 8; r++) a[r] = ctw<DIR>(a[r], s_tw[i * r]);
    dft8<DIR>(a);
}

// ---------------------------------------------------------------------------
// Twiddles; also zero column 256 of Ttmp (row p=256 of T is identically zero,
// and mode 4's Hermitian dual-write never touches column 256).
// ---------------------------------------------------------------------------
__global__ void tw_kernel() {
    int k = blockIdx.x * blockDim.x + threadIdx.x;
    if (k >= NF) return;
    float sp, cp;
    sincospif((float)k / 256.0f, &sp, &cp);
    g_tw[k] = make_float2(cp, -sp);
    g_Ttmp[k * NF + 256] = make_float2(0.f, 0.f);
}

// ---------------------------------------------------------------------------
// ex/ey tables. Compute t in [0,255], mirror-write conj at (512-t)&511.
// ---------------------------------------------------------------------------
__global__ void build_exp_kernel(const float* __restrict__ samples,
                                 const float* __restrict__ density) {
    int idx = blockIdx.x * blockDim.x + threadIdx.x;  // m*256 + t
    if (idx >= MSAMP * 256) return;
    int m = idx >> 8;
    int t = idx & 255;
    float p = (float)t;
    const float TWO_PI = 6.28318530717958647692f;
    float kx = samples[2*m], ky = samples[2*m+1];
    float sx, cx, sy, cy;
    sincosf(TWO_PI * kx * p, &sx, &cx);
    sincosf(TWO_PI * ky * p, &sy, &cy);
    float d = density[m] * (1.0f / 65536.0f);
    float2 exv = make_float2(cx * d, sx * d);
    float2 eyv = make_float2(cy, sy);
    g_ex[m * NF + t] = exv;
    g_ey[m * NF + t] = eyv;
    int tm = (NF - t) & (NF - 1);
    g_ex[m * NF + tm] = make_float2(exv.x, -exv.y);
    g_ey[m * NF + tm] = make_float2(eyv.x, -eyv.y);
    if (t == 0) {
        g_ex[m * NF + 256] = make_float2(0.f, 0.f);
        g_ey[m * NF + 256] = make_float2(0.f, 0.f);
    }
}

// ---------------------------------------------------------------------------
// T partials, Hermitian-halved: only p in [0,255] computed/stored.
// ---------------------------------------------------------------------------
__global__ __launch_bounds__(128, 4) void tpart_kernel() {
    __shared__ float2 sE[16 * 64]; // ex chunk [kk][p]
    __shared__ float2 sF[16 * 64]; // ey chunk [kk][q]

    int p0 = blockIdx.y * 64;      // 0..192
    int q0 = blockIdx.x * 64;
    int m0 = blockIdx.z * (MSAMP / KSPLIT);
    int tid = threadIdx.x;
    int ti = tid >> 4;   // 0..7
    int tj = tid & 15;   // 0..15

    u64t acc[8][4];
#pragma unroll
    for (int a = 0; a < 8; a++)
#pragma unroll
        for (int c = 0; c < 4; c++) acc[a][c] = 0ull;

    for (int k0 = 0; k0 < MSAMP / KSPLIT; k0 += 16) {
        __syncthreads();
#pragma unroll
        for (int u = tid; u < 1024; u += 128) {
            int kk  = u >> 6;
            int idx = u & 63;
            int m   = m0 + k0 + kk;
            sE[u] = g_ex[m * NF + p0 + idx];
            sF[u] = g_ey[m * NF + q0 + idx];
        }
        __syncthreads();

        const float4* sF4 = reinterpret_cast<const float4*>(sF);
#pragma unroll
        for (int kk = 0; kk < 16; ++kk) {
            int wbase = (kk * 64 + tj * 4) >> 1;
            float4 w01 = sF4[wbase];
            float4 w23 = sF4[wbase + 1];
            u64t W1[4], W2[4];
            W1[0] = pk2(w01.x, w01.x); W2[0] = pk2(-w01.y, w01.y);
            W1[1] = pk2(w01.z, w01.z); W2[1] = pk2(-w01.w, w01.w);
            W1[2] = pk2(w23.x, w23.x); W2[2] = pk2(-w23.y, w23.y);
            W1[3] = pk2(w23.z, w23.z); W2[3] = pk2(-w23.w, w23.w);
#pragma unroll
            for (int a = 0; a < 8; a++) {
                float2 av = sE[kk * 64 + ti + 8 * a];
                u64t avs = pk2(av.x, av.y);
                u64t avr = pk2(av.y, av.x);
#pragma unroll
                for (int c = 0; c < 4; c++) {
                    fma2(acc[a][c], W1[c], avs);
                    fma2(acc[a][c], W2[c], avr);
                }
            }
        }
    }

    float2* outp = g_Tpart + blockIdx.z * (256 * NF);
#pragma unroll
    for (int a = 0; a < 8; a++) {
        int p = p0 + ti + 8 * a;              // 0..255
#pragma unroll
        for (int c = 0; c < 4; c++) {
            int q = q0 + tj * 4 + c;
            outp[p * NF + q] = unpk2(acc[a][c]);
        }
    }
}

// ---------------------------------------------------------------------------
// FFT passes. 64 threads/line, 8 lines/CTA (512 threads).
// MODE 0: x fwd over j: load xr/xi row i (zero-pad) -> buf1[v][i] (transposed)
// MODE 1: fused middle, per (b,v): load buf1[v][i<256] (pad), FFT_i(+),
//         multiply TFr[v][u], reshuffle, IFFT_i(-), crop i<256,
//         transposed store buf2[i][v]
// MODE 2: final, per (b,i): load buf2[i][v], IFFT_v(-), crop j<256,
//         straight store out (scaled 1/512^2)
// MODE 4: T pass1, p in [0,255] (treduce fused); Hermitian dual write to
//         Ttmp[v][p] / Ttmp[v][512-p]=conj
// MODE 5: T pass2, per v: FFT over p -> u; straight real store TFr[v][u]
// ---------------------------------------------------------------------------
template<int MODE>
__global__ __launch_bounds__(512) void fft_pass_kernel(
    const float* __restrict__ xr, const float* __restrict__ xi,
    float2* __restrict__ out)
{
    __shared__ float2 s_tw[NF];
    __shared__ float2 s_buf[8][576];
    float2* sTr = &s_buf[0][0];    // reused as sT[line][k], stride TSTRIDE

    int t = threadIdx.x;
    int grp = t >> 6;          // line within CTA (0..7)
    int i   = t & 63;          // butterfly index
    float2* sline = &s_buf[grp][0];

    s_tw[t] = g_tw[t];

    int line = blockIdx.x * 8 + grp;

    float2 a[8];
    int b = 0, l2 = 0;

    if (MODE == 0) {
        b = line >> 8; l2 = line & 255;                 // l2 = image row i
        const float* pr = xr + ((b << 16) + (l2 << 8));
        const float* pi = xi + ((b << 16) + (l2 << 8));
#pragma unroll
        for (int r = 0; r < 8; r++) {
            if (r < 4) { int n = i + (r << 6); a[r] = make_float2(pr[n], pi[n]); }
            else a[r] = make_float2(0.f, 0.f);
        }
        fft512_stages<1>(a, sline, s_tw, i);

        // transposed store: buf1[v=k][l2], all 512 k
        __syncthreads();
#pragma unroll
        for (int r = 0; r < 8; r++) sTr[grp * TSTRIDE + ((r << 6) + i)] = a[r];
        __syncthreads();
        float2* dst = g_buf1 + b * NF2;
        int l2b = (blockIdx.x * 8) & 255;
#pragma unroll
        for (int w = 0; w < 4; w++) {
            int idx = w * 512 + t;
            int k   = idx >> 2;
            int gp  = idx & 3;
            float2 v0 = sTr[(2 * gp)     * TSTRIDE + k];
            float2 v1 = sTr[(2 * gp + 1) * TSTRIDE + k];
            float4* p4 = reinterpret_cast<float4*>(dst + k * NF + l2b + 2 * gp);
            *p4 = make_float4(v0.x, v0.y, v1.x, v1.y);
        }
    }
    else if (MODE == 1) {
        b = line >> 9; l2 = line & 511;                 // l2 = v
        const float2* src = g_buf1 + b * NF2 + l2 * NF;
#pragma unroll
        for (int r = 0; r < 8; r++)
            a[r] = (r < 4) ? src[i + (r << 6)] : make_float2(0.f, 0.f);

        fft512_stages<1>(a, sline, s_tw, i);            // -> a[r] = X[r*64+i]

        // pointwise multiply by real TF(u,v), u = r*64+i  (TFr stored [v][u])
        const float* tf = g_TFr + l2 * NF;
#pragma unroll
        for (int r = 0; r < 8; r++) {
            float s = tf[(r << 6) + i];
            a[r].x *= s; a[r].y *= s;
        }

        // reshuffle freq-order -> natural order for the inverse FFT
        __syncthreads();   // all stage-2 reads of sline complete
#pragma unroll
        for (int r = 0; r < 8; r++) sline[SPAD((r << 6) + i)] = a[r];
        __syncthreads();
#pragma unroll
        for (int r = 0; r < 8; r++) a[r] = sline[SPAD(i + (r << 6))];
        __syncthreads();   // reads complete before inverse stages overwrite

        fft512_stages<-1>(a, sline, s_tw, i);           // -> a[r] = x[r*64+i]

        // transposed store of cropped rows: buf2[i_out=k<256][l2]
        __syncthreads();
#pragma unroll
        for (int r = 0; r < 4; r++) sTr[grp * TSTRIDE + ((r << 6) + i)] = a[r];
        __syncthreads();
        float2* dst = g_buf2 + b * NF2;
        int l2b = (blockIdx.x * 8) & 511;
#pragma unroll
        for (int w = 0; w < 2; w++) {
            int idx = w * 512 + t;
            int k   = idx >> 2;                          // 0..255
            int gp  = idx & 3;
            float2 v0 = sTr[(2 * gp)     * TSTRIDE + k];
            float2 v1 = sTr[(2 * gp + 1) * TSTRIDE + k];
            float4* p4 = reinterpret_cast<float4*>(dst + k * NF + l2b + 2 * gp);
            *p4 = make_float4(v0.x, v0.y, v1.x, v1.y);
        }
    }
    else if (MODE == 2) {
        b = line >> 8; l2 = line & 255;                 // l2 = image row i
        const float2* src = g_buf2 + b * NF2 + l2 * NF;
#pragma unroll
        for (int r = 0; r < 8; r++) a[r] = src[i + (r << 6)];

        fft512_stages<-1>(a, sline, s_tw, i);           // -> a[r] = x[r*64+i]

        const float s = 1.0f / 262144.0f;               // 1/512^2
        float2* dst = out + (b << 16) + (l2 << 8);
#pragma unroll
        for (int r = 0; r < 4; r++) {
            int j = (r << 6) + i;
            dst[j] = make_float2(a[r].x * s, a[r].y * s);
        }
    }
    else if (MODE == 4) {
        l2 = line;                                      // l2 = p in [0,255]
        const float2* src = g_Tpart + l2 * NF;
#pragma unroll
        for (int r = 0; r < 8; r++) {
            float2 s = make_float2(0.f, 0.f);
#pragma unroll
            for (int z = 0; z < KSPLIT; z++)
                s = cadd(s, src[z * (256 * NF) + i + (r << 6)]);
            a[r] = s;
        }
        fft512_stages<1>(a, sline, s_tw, i);

        __syncthreads();
#pragma unroll
        for (int r = 0; r < 8; r++) sTr[grp * TSTRIDE + ((r << 6) + i)] = a[r];
        __syncthreads();
        // Hermitian dual write: Ttmp[v=k][p] straight, Ttmp[v][512-p] = conj.
        int l2b = blockIdx.x * 8;                       // 0..248
#pragma unroll
        for (int w = 0; w < 4; w++) {
            int idx = w * 512 + t;
            int k   = idx >> 2;
            int gp  = idx & 3;
            float2 v0 = sTr[(2 * gp)     * TSTRIDE + k];
            float2 v1 = sTr[(2 * gp + 1) * TSTRIDE + k];
            int c0 = l2b + 2 * gp;
            float4* p4 = reinterpret_cast<float4*>(g_Ttmp + k * NF + c0);
            *p4 = make_float4(v0.x, v0.y, v1.x, v1.y);
            if (c0 > 0) {
                g_Ttmp[k * NF + (NF - c0)]     = make_float2(v0.x, -v0.y);
                g_Ttmp[k * NF + (NF - c0 - 1)] = make_float2(v1.x, -v1.y);
            } else {
                g_Ttmp[k * NF + (NF - 1)]      = make_float2(v1.x, -v1.y);
            }
        }
    }
    else { // MODE 5
        l2 = line;                                      // l2 = v
        const float2* src = g_Ttmp + l2 * NF;
#pragma unroll
        for (int r = 0; r < 8; r++) a[r] = src[i + (r << 6)];

        fft512_stages<1>(a, sline, s_tw, i);            // -> a[r] = TF(u=r*64+i, v)

        // straight real store: TFr[v][u]  (warp-contiguous per r)
        float* dst = g_TFr + l2 * NF;
#pragma unroll
        for (int r = 0; r < 8; r++) dst[(r << 6) + i] = a[r].x;
    }
}

// ---------------------------------------------------------------------------
// Launch graph:
//   branch A (default stream): mode0                    (TF-independent head)
//   branch B (s2, forked):     tw -> build_exp -> tpart -> mode4 -> mode5
//   join, then mode1 (fused FFT*TF*IFFT) -> mode2 on default stream.
// Stream/events are host-side handles created ONCE on the first (eager) call
// so no creation APIs execute during graph capture; every call records the
// identical fork/join topology.
// ---------------------------------------------------------------------------
extern "C" void kernel_launch(void* const* d_in, const int* in_sizes, int n_in,
                              void* d_out, int out_size)
{
    const float* xr      = (const float*)d_in[0];
    const float* xi      = (const float*)d_in[1];
    const float* samples = (const float*)d_in[2];
    const float* density = (const float*)d_in[3];
    float2* out = (float2*)d_out;

    struct ForkCtx {
        cudaStream_t s2;
        cudaEvent_t evFork, evJoin;
        ForkCtx() {
            cudaStreamCreateWithFlags(&s2, cudaStreamNonBlocking);
            cudaEventCreateWithFlags(&evFork, cudaEventDisableTiming);
            cudaEventCreateWithFlags(&evJoin, cudaEventDisableTiming);
        }
    };
    static ForkCtx ctx;   // created on first (eager) call; reused every call

    // Fork s2 off the (possibly capturing) default stream.
    cudaEventRecord(ctx.evFork, 0);
    cudaStreamWaitEvent(ctx.s2, ctx.evFork, 0);

    // ---- branch B: Toeplitz kernel chain on s2 ----
    tw_kernel<<<2, 256, 0, ctx.s2>>>();
    build_exp_kernel<<<MSAMP, 256, 0, ctx.s2>>>(samples, density);
    tpart_kernel<<<dim3(8, 4, KSPLIT), 128, 0, ctx.s2>>>();
    fft_pass_kernel<4><<<256 / 8, 512, 0, ctx.s2>>>(nullptr, nullptr, nullptr);
    fft_pass_kernel<5><<<NF / 8, 512, 0, ctx.s2>>>(nullptr, nullptr, nullptr);

    // ---- branch A: x forward FFT over j on default stream ----
    fft_pass_kernel<0><<<BATCH * 256 / 8, 512>>>(xr, xi, nullptr);

    // Join: default stream waits for branch B (TFr ready).
    cudaEventRecord(ctx.evJoin, ctx.s2);
    cudaStreamWaitEvent(0, ctx.evJoin, 0);

    // ---- fused middle pass, then final inverse pass ----
    fft_pass_kernel<1><<<BATCH * 512 / 8, 512>>>(nullptr, nullptr, nullptr);
    fft_pass_kernel<2><<<BATCH * 256 / 8, 512>>>(nullptr, nullptr, out);
}